// round 11
// baseline (speedup 1.0000x reference)
#include <cuda_runtime.h>
#include <cuda_bf16.h>

#define NUM_FEATURES 64
#define MAX_CAV 5
#define NX 704
#define NY 200
#define NUM_PIXELS (NY * NX)          // 140800
#define TOTAL (MAX_CAV * NUM_PIXELS)  // 704000
#define N_PILLARS 60000
#define NGROUPS (NUM_PIXELS / 4)      // 35200 (= 1100 * 32, exact)
#define NBLOCKS 1100                  // <= wave-1 residency (148 SMs x 8 blocks)

// Inverse map: pixel -> pillar index + 1 (0 = empty).
// Invariant: all-zero before each kernel_launch. Zeroed at module load; phase 2
// zeroes every nonzero entry it consumes, restoring the invariant each call.
__device__ int g_pixmap[TOTAL];

// Monotonic grid barrier counter. Never reset: each execution advances it by
// exactly NBLOCKS (kernels are serialized), so a block arriving at value v
// waits for target ((v / NBLOCKS) + 1) * NBLOCKS. Graph-replay safe.
__device__ unsigned int g_bar;

__global__ void __launch_bounds__(256, 8) pp_fused(
    const int*   __restrict__ vc,     // [N, 4]
    const float* __restrict__ feat,   // [N, 64]
    float*       __restrict__ out)    // [5, 64, 200, 704]
{
    __shared__ int4 s_pm[32];

    int lane = threadIdx.x & 31;
    int w    = threadIdx.x >> 5;                 // 0..7 = channel octet
    int bx   = blockIdx.x;                       // 0..1099
    int g    = bx * 32 + lane;                   // 4-pixel group 0..NGROUPS-1

    // ---- Phase 1: build pixmap (first 60000 threads) ----
    int n = bx * 256 + threadIdx.x;
    if (n < N_PILLARS) {
        int4 co = __ldg(reinterpret_cast<const int4*>(vc) + n);  // (b, z, y, x)
        g_pixmap[co.x * NUM_PIXELS + co.z * NX + co.w] = n + 1;
    }

    // ---- Grid barrier ----
    __threadfence();             // make pixmap stores visible GPU-wide
    __syncthreads();             // all block's stores done before arrive
    if (threadIdx.x == 0) {
        unsigned int v = atomicAdd(&g_bar, 1u);
        unsigned int target = (v / NBLOCKS + 1u) * NBLOCKS;
        while (*(volatile unsigned int*)&g_bar < target) { }
        __threadfence();         // acquire: order pixmap reads after spin
    }
    __syncthreads();

    // ---- Phase 2: gather, 5 tiles (one per b), uniform work per block ----
    const float4* featv = reinterpret_cast<const float4*>(feat);
    const float4 zero = make_float4(0.f, 0.f, 0.f, 0.f);
    int c2 = 2 * w;

    #pragma unroll 1
    for (int b = 0; b < MAX_CAV; b++) {
        if (w == 0) {
            int4* pmp = reinterpret_cast<int4*>(g_pixmap) + b * NGROUPS + g;
            int4 pm = *pmp;
            s_pm[lane] = pm;
            if ((pm.x | pm.y | pm.z | pm.w) != 0)
                *pmp = make_int4(0, 0, 0, 0);    // self-clear for next call
        }
        __syncthreads();

        int4 pmv = s_pm[lane];
        int p0 = pmv.x, p1 = pmv.y, p2 = pmv.z, p3 = pmv.w;

        int f0 = (p0 > 0 ? (p0 - 1) : 0) * (NUM_FEATURES / 4) + c2;
        int f1 = (p1 > 0 ? (p1 - 1) : 0) * (NUM_FEATURES / 4) + c2;
        int f2 = (p2 > 0 ? (p2 - 1) : 0) * (NUM_FEATURES / 4) + c2;
        int f3 = (p3 > 0 ? (p3 - 1) : 0) * (NUM_FEATURES / 4) + c2;

        float4* obase = reinterpret_cast<float4*>(out)
                      + (b * NUM_FEATURES + 8 * w) * NGROUPS + g;

        // Half 1: channels [8w, 8w+4)
        {
            float4 v0 = (p0 > 0) ? __ldg(featv + f0) : zero;
            float4 v1 = (p1 > 0) ? __ldg(featv + f1) : zero;
            float4 v2 = (p2 > 0) ? __ldg(featv + f2) : zero;
            float4 v3 = (p3 > 0) ? __ldg(featv + f3) : zero;
            obase[0 * NGROUPS] = make_float4(v0.x, v1.x, v2.x, v3.x);
            obase[1 * NGROUPS] = make_float4(v0.y, v1.y, v2.y, v3.y);
            obase[2 * NGROUPS] = make_float4(v0.z, v1.z, v2.z, v3.z);
            obase[3 * NGROUPS] = make_float4(v0.w, v1.w, v2.w, v3.w);
        }
        // Half 2: channels [8w+4, 8w+8)
        {
            float4 v0 = (p0 > 0) ? __ldg(featv + f0 + 1) : zero;
            float4 v1 = (p1 > 0) ? __ldg(featv + f1 + 1) : zero;
            float4 v2 = (p2 > 0) ? __ldg(featv + f2 + 1) : zero;
            float4 v3 = (p3 > 0) ? __ldg(featv + f3 + 1) : zero;
            obase[4 * NGROUPS] = make_float4(v0.x, v1.x, v2.x, v3.x);
            obase[5 * NGROUPS] = make_float4(v0.y, v1.y, v2.y, v3.y);
            obase[6 * NGROUPS] = make_float4(v0.z, v1.z, v2.z, v3.z);
            obase[7 * NGROUPS] = make_float4(v0.w, v1.w, v2.w, v3.w);
        }
        __syncthreads();   // s_pm reuse safety
    }
}

extern "C" void kernel_launch(void* const* d_in, const int* in_sizes, int n_in,
                              void* d_out, int out_size)
{
    const int*   vc   = (const int*)d_in[0];    // voxel_coords int32 [60000, 4]
    const float* feat = (const float*)d_in[1];  // pillar_features f32 [60000, 64]
    float* out = (float*)d_out;                 // [5, 64, 200, 704] f32

    pp_fused<<<NBLOCKS, 256>>>(vc, feat, out);
}

// round 12
// speedup vs baseline: 1.2319x; 1.2319x over previous
#include <cuda_runtime.h>
#include <cuda_bf16.h>

#define NUM_FEATURES 64
#define MAX_CAV 5
#define NX 704
#define NY 200
#define NUM_PIXELS (NY * NX)          // 140800
#define TOTAL (MAX_CAV * NUM_PIXELS)  // 704000
#define N_PILLARS 60000
#define NGROUPS (NUM_PIXELS / 4)      // 35200 (= 1100 * 32, exact)

// Inverse map: pixel -> pillar index + 1 (0 = empty).
// Invariant: all-zero before each kernel_launch. Zeroed at module load; the
// gather kernel zeroes every nonzero entry it consumes, restoring the
// invariant each call. Output is a pure function of the current inputs.
__device__ int g_pixmap[TOTAL];

// Kernel A: scatter (pillar+1) into the pixmap (indices are a permutation -> no collisions).
__global__ void __launch_bounds__(256) pp_build_pixmap(const int* __restrict__ vc)
{
    int n = blockIdx.x * blockDim.x + threadIdx.x;
    if (n >= N_PILLARS) return;
    int4 co = __ldg(reinterpret_cast<const int4*>(vc) + n);  // (b, z, y, x)
    g_pixmap[co.x * NUM_PIXELS + co.z * NX + co.w] = n + 1;
}

// Kernel B: streaming gather + self-clearing pixmap.
//   block = (b, 32 consecutive 4-pixel groups) x 16 channel-quads = 512 thr.
//   Each thread: 4 independent 16B feature loads (one float4 per sub-pixel,
//   channels [4cq, 4cq+4)) + 4 independent float4 stores (each warp store =
//   512B contiguous). Warp 0 stages the 32 pixmap int4s into smem and zeroes
//   the nonzero ones.
__global__ void __launch_bounds__(512, 4) pp_gather(
    const float* __restrict__ feat,   // [N, 64]
    float*       __restrict__ out)    // [5, 64, 200, 704]
{
    __shared__ int4 s_pm[32];

    int lane = threadIdx.x & 31;
    int cq   = threadIdx.x >> 5;                 // 0..15 = channel quad
    int g    = blockIdx.x * 32 + lane;           // 4-pixel group 0..NGROUPS-1
    int b    = blockIdx.z;                       // 0..4

    if (cq == 0) {
        int4* pmp = reinterpret_cast<int4*>(g_pixmap) + b * NGROUPS + g;
        int4 pm = *pmp;
        s_pm[lane] = pm;
        if ((pm.x | pm.y | pm.z | pm.w) != 0)
            *pmp = make_int4(0, 0, 0, 0);        // self-clear for next call
    }
    __syncthreads();

    int4 pmv = s_pm[lane];
    int p0 = pmv.x, p1 = pmv.y, p2 = pmv.z, p3 = pmv.w;

    const float4* featv = reinterpret_cast<const float4*>(feat);
    const float4 zero = make_float4(0.f, 0.f, 0.f, 0.f);

    // One float4 per sub-pixel: channels [4cq, 4cq+4). Empty sub-pixels read
    // pillar 0's row (L1 broadcast) and select zero.
    int f0 = (p0 > 0 ? (p0 - 1) : 0) * (NUM_FEATURES / 4) + cq;
    int f1 = (p1 > 0 ? (p1 - 1) : 0) * (NUM_FEATURES / 4) + cq;
    int f2 = (p2 > 0 ? (p2 - 1) : 0) * (NUM_FEATURES / 4) + cq;
    int f3 = (p3 > 0 ? (p3 - 1) : 0) * (NUM_FEATURES / 4) + cq;

    float4 v0 = (p0 > 0) ? __ldg(featv + f0) : zero;
    float4 v1 = (p1 > 0) ? __ldg(featv + f1) : zero;
    float4 v2 = (p2 > 0) ? __ldg(featv + f2) : zero;
    float4 v3 = (p3 > 0) ? __ldg(featv + f3) : zero;

    // 32-bit output offset (float4 units): channels 4cq..4cq+3.
    float4* obase = reinterpret_cast<float4*>(out)
                  + (b * NUM_FEATURES + 4 * cq) * NGROUPS + g;

    obase[0 * NGROUPS] = make_float4(v0.x, v1.x, v2.x, v3.x);
    obase[1 * NGROUPS] = make_float4(v0.y, v1.y, v2.y, v3.y);
    obase[2 * NGROUPS] = make_float4(v0.z, v1.z, v2.z, v3.z);
    obase[3 * NGROUPS] = make_float4(v0.w, v1.w, v2.w, v3.w);
}

extern "C" void kernel_launch(void* const* d_in, const int* in_sizes, int n_in,
                              void* d_out, int out_size)
{
    const int*   vc   = (const int*)d_in[0];    // voxel_coords int32 [60000, 4]
    const float* feat = (const float*)d_in[1];  // pillar_features f32 [60000, 64]
    float* out = (float*)d_out;                 // [5, 64, 200, 704] f32

    pp_build_pixmap<<<(N_PILLARS + 255) / 256, 256>>>(vc);

    dim3 grid(NGROUPS / 32, 1, MAX_CAV);   // (1100, 1, 5), 512 threads each
    pp_gather<<<grid, 512>>>(feat, out);
}

// round 13
// speedup vs baseline: 1.3403x; 1.0880x over previous
#include <cuda_runtime.h>
#include <cuda_bf16.h>

#define NUM_FEATURES 64
#define MAX_CAV 5
#define NX 704
#define NY 200
#define NUM_PIXELS (NY * NX)          // 140800
#define TOTAL (MAX_CAV * NUM_PIXELS)  // 704000
#define N_PILLARS 60000
#define NGROUPS (NUM_PIXELS / 4)      // 35200 (= 1100 * 32, exact)

// Inverse map: pixel -> pillar index + 1 (0 = empty).
// Invariant: all-zero before each kernel_launch. Zeroed at module load; the
// gather kernel zeroes every nonzero entry it consumes (after the block
// barrier orders the clear behind all warps' reads), restoring the invariant
// each call. Output is a pure function of the current inputs.
__device__ int g_pixmap[TOTAL];

// Kernel A: scatter (pillar+1) into the pixmap (indices are a permutation -> no collisions).
__global__ void __launch_bounds__(256) pp_build_pixmap(const int* __restrict__ vc)
{
    int n = blockIdx.x * blockDim.x + threadIdx.x;
    if (n >= N_PILLARS) return;
    int4 co = __ldg(reinterpret_cast<const int4*>(vc) + n);  // (b, z, y, x)
    g_pixmap[co.x * NUM_PIXELS + co.z * NX + co.w] = n + 1;
}

// Kernel B: streaming gather + self-clearing pixmap.
//   block = (b, 32 consecutive 4-pixel groups); warp w = channel octet.
//   Every warp loads its pixmap int4 directly (parallel fetches, 7/8 hit L1),
//   consumes it into registers, THEN the block barrier, THEN warp 0 clears.
//   Two half-transposes per thread, int32 index math, <=32 regs -> 8 blk/SM.
//   Warp stores are 512B contiguous float4.
__global__ void __launch_bounds__(256, 8) pp_gather(
    const float* __restrict__ feat,   // [N, 64]
    float*       __restrict__ out)    // [5, 64, 200, 704]
{
    int lane = threadIdx.x & 31;
    int w    = threadIdx.x >> 5;                 // 0..7 = channel octet
    int g    = blockIdx.x * 32 + lane;           // 4-pixel group 0..NGROUPS-1
    int b    = blockIdx.z;                       // 0..4

    int4* pmp = reinterpret_cast<int4*>(g_pixmap) + b * NGROUPS + g;
    int4 pmv = *pmp;                             // all 8 warps load in parallel
    int p0 = pmv.x, p1 = pmv.y, p2 = pmv.z, p3 = pmv.w;

    // Consume pm into register-resident offsets BEFORE the barrier.
    int c2 = 2 * w;
    int f0 = (p0 > 0 ? (p0 - 1) : 0) * (NUM_FEATURES / 4) + c2;
    int f1 = (p1 > 0 ? (p1 - 1) : 0) * (NUM_FEATURES / 4) + c2;
    int f2 = (p2 > 0 ? (p2 - 1) : 0) * (NUM_FEATURES / 4) + c2;
    int f3 = (p3 > 0 ? (p3 - 1) : 0) * (NUM_FEATURES / 4) + c2;

    __syncthreads();   // all warps' pixmap reads happen-before the clear

    if (w == 0 && (p0 | p1 | p2 | p3) != 0)
        *pmp = make_int4(0, 0, 0, 0);            // self-clear for next call

    const float4* featv = reinterpret_cast<const float4*>(feat);
    const float4 zero = make_float4(0.f, 0.f, 0.f, 0.f);

    float4* obase = reinterpret_cast<float4*>(out)
                  + (b * NUM_FEATURES + 8 * w) * NGROUPS + g;

    // Half 1: channels [8w, 8w+4)
    {
        float4 v0 = (p0 > 0) ? __ldg(featv + f0) : zero;
        float4 v1 = (p1 > 0) ? __ldg(featv + f1) : zero;
        float4 v2 = (p2 > 0) ? __ldg(featv + f2) : zero;
        float4 v3 = (p3 > 0) ? __ldg(featv + f3) : zero;
        obase[0 * NGROUPS] = make_float4(v0.x, v1.x, v2.x, v3.x);
        obase[1 * NGROUPS] = make_float4(v0.y, v1.y, v2.y, v3.y);
        obase[2 * NGROUPS] = make_float4(v0.z, v1.z, v2.z, v3.z);
        obase[3 * NGROUPS] = make_float4(v0.w, v1.w, v2.w, v3.w);
    }

    // Half 2: channels [8w+4, 8w+8)
    {
        float4 v0 = (p0 > 0) ? __ldg(featv + f0 + 1) : zero;
        float4 v1 = (p1 > 0) ? __ldg(featv + f1 + 1) : zero;
        float4 v2 = (p2 > 0) ? __ldg(featv + f2 + 1) : zero;
        float4 v3 = (p3 > 0) ? __ldg(featv + f3 + 1) : zero;
        obase[4 * NGROUPS] = make_float4(v0.x, v1.x, v2.x, v3.x);
        obase[5 * NGROUPS] = make_float4(v0.y, v1.y, v2.y, v3.y);
        obase[6 * NGROUPS] = make_float4(v0.z, v1.z, v2.z, v3.z);
        obase[7 * NGROUPS] = make_float4(v0.w, v1.w, v2.w, v3.w);
    }
}

extern "C" void kernel_launch(void* const* d_in, const int* in_sizes, int n_in,
                              void* d_out, int out_size)
{
    const int*   vc   = (const int*)d_in[0];    // voxel_coords int32 [60000, 4]
    const float* feat = (const float*)d_in[1];  // pillar_features f32 [60000, 64]
    float* out = (float*)d_out;                 // [5, 64, 200, 704] f32

    pp_build_pixmap<<<(N_PILLARS + 255) / 256, 256>>>(vc);

    dim3 grid(NGROUPS / 32, 1, MAX_CAV);   // (1100, 1, 5)
    pp_gather<<<grid, 256>>>(feat, out);
}